// round 2
// baseline (speedup 1.0000x reference)
#include <cuda_runtime.h>
#include <cstdint>

// CompressK: mean-pool over sliding windows of 32 rows, stride 16.
// k: (BATCH*SEQ_LEN, HEAD_NUM_K=4, HEAD_DIM=128) fp32  -> row = 512 floats
// out: (4092, 4, 128) fp32  followed by cu_comp (BATCH+1) as fp32 values.

#define BATCH 4
#define SEQ_LEN 16384
#define ROW_FLOATS 512            // 4 heads * 128 dim
#define ROW_F4 128                // ROW_FLOATS / 4
#define CHUNKS_PER_BATCH 1023     // (16384-32)/16 + 1
#define TOTAL_CHUNKS (BATCH * CHUNKS_PER_BATCH)   // 4092
#define CH 8                      // chunks per CUDA block
#define BLOCKS_PER_BATCH ((CHUNKS_PER_BATCH + CH - 1) / CH)  // 128
#define OUT_FLOATS ((size_t)TOTAL_CHUNKS * ROW_FLOATS)       // 2,095,104

__global__ __launch_bounds__(ROW_F4) void compress_k_kernel(
    const float4* __restrict__ k4, float4* __restrict__ out4)
{
    const int tid = threadIdx.x;                 // 0..127, float4 column
    const int batch = blockIdx.x / BLOCKS_PER_BATCH;
    const int bi    = blockIdx.x % BLOCKS_PER_BATCH;

    const int c_begin = bi * CH;                 // first local chunk
    int nch = CHUNKS_PER_BATCH - c_begin;
    if (nch > CH) nch = CH;
    if (nch <= 0) return;

    // base input row of the first 16-row block this CUDA block needs
    const size_t base_row = (size_t)batch * SEQ_LEN + (size_t)c_begin * 16;
    const float4* src = k4 + base_row * ROW_F4 + tid;

    const float inv32 = 1.0f / 32.0f;

    float4 sPrev = make_float4(0.f, 0.f, 0.f, 0.f);

    // block-sums j = 0..nch ; chunk (c_begin + j - 1) = (S_{j-1} + S_j) / 32
    for (int j = 0; j <= nch; ++j) {
        const float4* p = src + (size_t)j * 16 * ROW_F4;
        float4 s = make_float4(0.f, 0.f, 0.f, 0.f);
        #pragma unroll
        for (int r = 0; r < 16; ++r) {
            float4 v = p[(size_t)r * ROW_F4];
            s.x += v.x; s.y += v.y; s.z += v.z; s.w += v.w;
        }
        if (j > 0) {
            float4 o;
            o.x = (sPrev.x + s.x) * inv32;
            o.y = (sPrev.y + s.y) * inv32;
            o.z = (sPrev.z + s.z) * inv32;
            o.w = (sPrev.w + s.w) * inv32;
            const size_t oc = (size_t)batch * CHUNKS_PER_BATCH + c_begin + (j - 1);
            out4[oc * ROW_F4 + tid] = o;
        }
        sPrev = s;
    }
}

// Write cu_comp tail as float values (output buffer is fp32).
__global__ void cu_comp_tail_kernel(float* __restrict__ out)
{
    int i = threadIdx.x;
    if (i <= BATCH) {
        out[OUT_FLOATS + i] = (float)(i * CHUNKS_PER_BATCH);
    }
}

extern "C" void kernel_launch(void* const* d_in, const int* in_sizes, int n_in,
                              void* d_out, int out_size)
{
    const float4* k4 = (const float4*)d_in[0];
    float* out = (float*)d_out;

    dim3 grid(BATCH * BLOCKS_PER_BATCH);
    compress_k_kernel<<<grid, ROW_F4>>>(k4, (float4*)d_out);

    if ((size_t)out_size >= OUT_FLOATS + BATCH + 1) {
        cu_comp_tail_kernel<<<1, 32>>>(out);
    }
}

// round 3
// speedup vs baseline: 1.4907x; 1.4907x over previous
#include <cuda_runtime.h>
#include <cstdint>

// CompressK: mean-pool over sliding windows of 32 rows, stride 16.
// k: (BATCH*SEQ_LEN, 4, 128) fp32 -> row = 512 floats = 128 float4
// out: (4092, 4, 128) fp32 followed by cu_comp (BATCH+1) as fp32 values.
//
// Block-sum sharing: chunk c = (S_c + S_{c+1}) / 32 where S_j = sum of
// 16-row block j. A CUDA block computing CH consecutive chunks computes
// CH+1 block-sums -> reads (CH+1)/(2*CH) of the naive 2x traffic.

#define BATCH 4
#define SEQ_LEN 16384
#define ROW_F4 128                // 512 floats / 4
#define CHUNKS_PER_BATCH 1023     // (16384-32)/16 + 1
#define TOTAL_CHUNKS (BATCH * CHUNKS_PER_BATCH)   // 4092
#define CH 4                      // chunks per CUDA block
#define BLOCKS_PER_BATCH ((CHUNKS_PER_BATCH + CH - 1) / CH)  // 256
#define OUT_FLOATS ((size_t)TOTAL_CHUNKS * ROW_F4 * 4)       // 2,095,104

__global__ __launch_bounds__(ROW_F4) void compress_k_kernel(
    const float4* __restrict__ k4, float4* __restrict__ out4,
    float* __restrict__ out_scalar)
{
    const int tid = threadIdx.x;                 // 0..127, float4 column
    const int batch = blockIdx.x / BLOCKS_PER_BATCH;
    const int bi    = blockIdx.x % BLOCKS_PER_BATCH;

    // Fused cu_comp tail (fp32 values; exact for these magnitudes)
    if (blockIdx.x == 0 && tid <= BATCH) {
        out_scalar[OUT_FLOATS + tid] = (float)(tid * CHUNKS_PER_BATCH);
    }

    const int c_begin = bi * CH;                 // first local chunk
    int nch = CHUNKS_PER_BATCH - c_begin;
    if (nch > CH) nch = CH;
    if (nch <= 0) return;

    const size_t base_row = (size_t)batch * SEQ_LEN + (size_t)c_begin * 16;
    const float4* src = k4 + base_row * ROW_F4 + tid;

    const float inv32 = 1.0f / 32.0f;

    float4 sPrev = make_float4(0.f, 0.f, 0.f, 0.f);

    // block-sums j = 0..nch ; chunk (c_begin + j - 1) = (S_{j-1} + S_j)/32
    for (int j = 0; j <= nch; ++j) {
        const float4* p = src + (size_t)j * 16 * ROW_F4;

        // 4 independent accumulator chains -> shorter dep chains,
        // lets ptxas batch all 16 LDG.128 up front.
        float4 a0 = make_float4(0.f, 0.f, 0.f, 0.f);
        float4 a1 = make_float4(0.f, 0.f, 0.f, 0.f);
        float4 a2 = make_float4(0.f, 0.f, 0.f, 0.f);
        float4 a3 = make_float4(0.f, 0.f, 0.f, 0.f);
        #pragma unroll
        for (int r = 0; r < 4; ++r) {
            float4 v0 = p[(size_t)(4 * r + 0) * ROW_F4];
            float4 v1 = p[(size_t)(4 * r + 1) * ROW_F4];
            float4 v2 = p[(size_t)(4 * r + 2) * ROW_F4];
            float4 v3 = p[(size_t)(4 * r + 3) * ROW_F4];
            a0.x += v0.x; a0.y += v0.y; a0.z += v0.z; a0.w += v0.w;
            a1.x += v1.x; a1.y += v1.y; a1.z += v1.z; a1.w += v1.w;
            a2.x += v2.x; a2.y += v2.y; a2.z += v2.z; a2.w += v2.w;
            a3.x += v3.x; a3.y += v3.y; a3.z += v3.z; a3.w += v3.w;
        }
        float4 s;
        s.x = (a0.x + a1.x) + (a2.x + a3.x);
        s.y = (a0.y + a1.y) + (a2.y + a3.y);
        s.z = (a0.z + a1.z) + (a2.z + a3.z);
        s.w = (a0.w + a1.w) + (a2.w + a3.w);

        if (j > 0) {
            float4 o;
            o.x = (sPrev.x + s.x) * inv32;
            o.y = (sPrev.y + s.y) * inv32;
            o.z = (sPrev.z + s.z) * inv32;
            o.w = (sPrev.w + s.w) * inv32;
            const size_t oc = (size_t)batch * CHUNKS_PER_BATCH + c_begin + (j - 1);
            out4[oc * ROW_F4 + tid] = o;
        }
        sPrev = s;
    }
}

extern "C" void kernel_launch(void* const* d_in, const int* in_sizes, int n_in,
                              void* d_out, int out_size)
{
    const float4* k4 = (const float4*)d_in[0];

    dim3 grid(BATCH * BLOCKS_PER_BATCH);
    compress_k_kernel<<<grid, ROW_F4>>>(k4, (float4*)d_out, (float*)d_out);
}